// round 11
// baseline (speedup 1.0000x reference)
#include <cuda_runtime.h>

// ---------------- static device scratch (no allocations allowed) ----------------
#define NN_MAX 200000
#define NE_MAX 300000

__device__ __align__(16) float g_emb2[(size_t)NN_MAX * 256];    // leaky(mem@W_bs+b)
__device__ __align__(16) float g_nodeLR[(size_t)NN_MAX * 128];  // [nodeL | nodeR]
__device__ __align__(16) float g_relLR[(size_t)NE_MAX * 128];   // [relL | relR]
__device__ __align__(16) float g_Cmat[256 * 128];               // W_proj@[Wl_a | Wr_a]
__device__ __align__(16) float g_Dmat[256 * 128];               // W_proj@[Wl_b | Wr_b]
__device__ __align__(16) float g_cb[128];
__device__ __align__(16) float g_db[128];
__device__ __align__(16) float g_qs[128 * 32];
__device__ __align__(16) float g_qr[128 * 64];
__device__ __align__(16) float g_qtab[128 * 128];               // per-query [L|R] additive table
__device__ float g_logits[NE_MAX];
__device__ float g_ex[NE_MAX];
__device__ unsigned g_segmax[NN_MAX];
__device__ float g_denom[NN_MAX];

__device__ __forceinline__ float leaky_f(float x) { return x > 0.f ? x : 0.01f * x; }

// order-preserving float->uint key for atomicMax
__device__ __forceinline__ unsigned fkey(float f) {
    int i = __float_as_int(f);
    return (i >= 0) ? ((unsigned)i | 0x80000000u) : ~(unsigned)i;
}
__device__ __forceinline__ float funkey(unsigned u) {
    int i = (u & 0x80000000u) ? (int)(u & 0x7FFFFFFFu) : ~(int)u;
    return __int_as_float(i);
}

// ---- packed fp32x2 helpers (Blackwell FFMA2 path) ----
__device__ __forceinline__ unsigned long long pack_dup(float v) {
    unsigned long long r;
    asm("mov.b64 %0, {%1, %1};" : "=l"(r) : "f"(v));
    return r;
}
__device__ __forceinline__ void ffma2(unsigned long long& d, unsigned long long a,
                                      unsigned long long b) {
    asm("fma.rn.f32x2 %0, %1, %2, %0;" : "+l"(d) : "l"(a), "l"(b));
}
__device__ __forceinline__ void unpack2(unsigned long long v, float& lo, float& hi) {
    asm("mov.b64 {%0, %1}, %2;" : "=f"(lo), "=f"(hi) : "l"(v));
}

// aligned 32-byte operand bundle: float4x2 view for LDS.128, u64 view for FFMA2
union __align__(16) Vec8 {
    float4 v4[2];
    float f[8];
    unsigned long long u2[4];
};

// ---------------- init ----------------
__global__ void init_kernel(float* __restrict__ out, int Nn, int Osz) {
    int i = blockIdx.x * blockDim.x + threadIdx.x;
    if (i < Nn) { g_denom[i] = 0.f; g_segmax[i] = 0u; }
    if (i < Osz) out[i] = 0.f;
}

// ---------------- prep: fold small matrices ----------------
// Cmat[k][j] (j<64):  sum_m W_proj[k][m]*Wl[m][j]        (hvi path, left)
//           (j>=64):  sum_m W_proj[k][m]*Wr[m][j-64]     (hvj path, right)
// Dmat: same with Wl/Wr rows 64..127 (rel path).  cb/db: b_proj through same rows.
__global__ void prep1_kernel(const float* __restrict__ W_proj, const float* __restrict__ b_proj,
                             const float* __restrict__ W_static, const float* __restrict__ b_static,
                             const float* __restrict__ Wl, const float* __restrict__ Wr,
                             const float* __restrict__ qse, const float* __restrict__ qre) {
    int idx = blockIdx.x * blockDim.x + threadIdx.x;
    if (idx < 32768) {
        int k = idx >> 7, j = idx & 127;
        const float* W = (j < 64) ? Wl : Wr; int jj = j & 63;
        float s = 0.f;
        #pragma unroll 8
        for (int m = 0; m < 64; m++) s += W_proj[k * 64 + m] * W[m * 64 + jj];
        g_Cmat[k * 128 + j] = s;
    } else if (idx < 65536) {
        int t = idx - 32768; int k = t >> 7, j = t & 127;
        const float* W = (j < 64) ? Wl : Wr; int jj = j & 63;
        float s = 0.f;
        #pragma unroll 8
        for (int m = 0; m < 64; m++) s += W_proj[k * 64 + m] * W[(64 + m) * 64 + jj];
        g_Dmat[k * 128 + j] = s;
    } else if (idx < 65664) {
        int j = idx - 65536; const float* W = (j < 64) ? Wl : Wr; int jj = j & 63;
        float s = 0.f;
        for (int m = 0; m < 64; m++) s += b_proj[m] * W[m * 64 + jj];
        g_cb[j] = s;
    } else if (idx < 65792) {
        int j = idx - 65664; const float* W = (j < 64) ? Wl : Wr; int jj = j & 63;
        float s = 0.f;
        for (int m = 0; m < 64; m++) s += b_proj[m] * W[(64 + m) * 64 + jj];
        g_db[j] = s;
    } else if (idx < 69888) {
        int t2 = idx - 65792; int q = t2 >> 5, t = t2 & 31;
        float s = b_static[t];
        for (int k = 0; k < 128; k++) s += qse[q * 128 + k] * W_static[k * 32 + t];
        g_qs[q * 32 + t] = s;
    } else if (idx < 78080) {
        int t2 = idx - 69888; int q = t2 >> 6, m = t2 & 63;
        float s = b_proj[m];
        for (int k = 0; k < 256; k++) s += qre[q * 256 + k] * W_proj[k * 64 + m];
        g_qr[q * 64 + m] = s;
    }
}

// qtab[q][j<64]  = bl[j]  + qs[q]@Wl[128:160,j] + qr[q]@Wl[160:224,j]
// qtab[q][j>=64] = br[jj] + qs[q]@Wr[128:160,jj] + qr[q]@Wr[160:224,jj]
__global__ void prep2_kernel(const float* __restrict__ Wl, const float* __restrict__ bl,
                             const float* __restrict__ Wr, const float* __restrict__ br) {
    int idx = blockIdx.x * blockDim.x + threadIdx.x;
    if (idx >= 16384) return;
    int q = idx >> 7, j = idx & 127;
    const float *W, *b; int jj;
    if (j < 64) { W = Wl; b = bl; jj = j; } else { W = Wr; b = br; jj = j - 64; }
    float s = b[jj];
    for (int t = 0; t < 32; t++) s += g_qs[q * 32 + t] * W[(128 + t) * 64 + jj];
    for (int m = 0; m < 64; m++) s += g_qr[q * 64 + m] * W[(160 + m) * 64 + jj];
    g_qtab[q * 128 + j] = s;
}

// ---------------- tiled fp32 GEMM: FFMA2 + double-buffered smem + reg prefetch --
// C = act(A[MxK] @ B[KxN] + bias[N]); BM=BN=128, BK=16, 256 thr, 8x8 reg tile.
// Accumulators packed f32x2 along rows (row pairs free from the float4 smem
// load); B dup-packed per k-step. One barrier per K-tile.
template <int ACT>
__global__ void __launch_bounds__(256, 2) gemm_kernel(
    const float* __restrict__ A, const float* __restrict__ B,
    const float* __restrict__ bias, float* __restrict__ C,
    int M, int N, int K) {
    __shared__ float As[2][16][132];  // transposed tile, padded
    __shared__ float Bs[2][16][128];
    const int tid = threadIdx.x;
    const int bm = blockIdx.y << 7;
    const int bn = blockIdx.x << 7;
    const int trow = (tid >> 4) << 3;
    const int tcol = (tid & 15) << 3;

    // per-thread load coordinates (2 float4 each for A and B)
    const int ar0 = tid >> 2,          ac0 = (tid & 3) << 2;   // A part 0
    const int ar1 = (tid + 256) >> 2,  ac1 = ac0;               // A part 1
    const int br0 = tid >> 5,          bc0 = (tid & 31) << 2;   // B part 0
    const int br1 = (tid + 256) >> 5,  bc1 = bc0;               // B part 1

    // packed accumulators: accp[j][x] holds rows (trow+2j, trow+2j+1), col tcol+x
    unsigned long long accp[4][8];
    #pragma unroll
    for (int j = 0; j < 4; j++)
        #pragma unroll
        for (int x = 0; x < 8; x++) accp[j][x] = 0ull;

    // prologue: fetch tile 0, commit to buffer 0
    float4 a0 = make_float4(0.f,0.f,0.f,0.f), a1 = a0, b0, b1;
    if (bm + ar0 < M) a0 = *(const float4*)(A + (size_t)(bm + ar0) * K + ac0);
    if (bm + ar1 < M) a1 = *(const float4*)(A + (size_t)(bm + ar1) * K + ac1);
    b0 = *(const float4*)(B + (size_t)br0 * N + bn + bc0);
    b1 = *(const float4*)(B + (size_t)br1 * N + bn + bc1);
    As[0][ac0 + 0][ar0] = a0.x; As[0][ac0 + 1][ar0] = a0.y;
    As[0][ac0 + 2][ar0] = a0.z; As[0][ac0 + 3][ar0] = a0.w;
    As[0][ac1 + 0][ar1] = a1.x; As[0][ac1 + 1][ar1] = a1.y;
    As[0][ac1 + 2][ar1] = a1.z; As[0][ac1 + 3][ar1] = a1.w;
    *(float4*)&Bs[0][br0][bc0] = b0;
    *(float4*)&Bs[0][br1][bc1] = b1;
    __syncthreads();

    int s = 0;
    for (int k0 = 0; k0 < K; k0 += 16) {
        const int kn = k0 + 16;
        // prefetch next tile into registers (overlaps the FMA loop)
        if (kn < K) {
            a0 = make_float4(0.f,0.f,0.f,0.f); a1 = a0;
            if (bm + ar0 < M) a0 = *(const float4*)(A + (size_t)(bm + ar0) * K + kn + ac0);
            if (bm + ar1 < M) a1 = *(const float4*)(A + (size_t)(bm + ar1) * K + kn + ac1);
            b0 = *(const float4*)(B + (size_t)(kn + br0) * N + bn + bc0);
            b1 = *(const float4*)(B + (size_t)(kn + br1) * N + bn + bc1);
        }

        #pragma unroll
        for (int k = 0; k < 16; k++) {
            Vec8 av, bv;   // aligned unions: LDS.128 in, row-pair u64 out
            av.v4[0] = *(const float4*)&As[s][k][trow];
            av.v4[1] = *(const float4*)&As[s][k][trow + 4];
            bv.v4[0] = *(const float4*)&Bs[s][k][tcol];
            bv.v4[1] = *(const float4*)&Bs[s][k][tcol + 4];
            unsigned long long bd[8];
            #pragma unroll
            for (int x = 0; x < 8; x++) bd[x] = pack_dup(bv.f[x]);
            #pragma unroll
            for (int j = 0; j < 4; j++)
                #pragma unroll
                for (int x = 0; x < 8; x++) ffma2(accp[j][x], av.u2[j], bd[x]);
        }

        // commit prefetched tile to the other buffer
        if (kn < K) {
            const int t = s ^ 1;
            As[t][ac0 + 0][ar0] = a0.x; As[t][ac0 + 1][ar0] = a0.y;
            As[t][ac0 + 2][ar0] = a0.z; As[t][ac0 + 3][ar0] = a0.w;
            As[t][ac1 + 0][ar1] = a1.x; As[t][ac1 + 1][ar1] = a1.y;
            As[t][ac1 + 2][ar1] = a1.z; As[t][ac1 + 3][ar1] = a1.w;
            *(float4*)&Bs[t][br0][bc0] = b0;
            *(float4*)&Bs[t][br1][bc1] = b1;
            __syncthreads();
            s = t;
        }
    }

    #pragma unroll
    for (int j = 0; j < 4; j++) {
        float rlo[8], rhi[8];
        #pragma unroll
        for (int x = 0; x < 8; x++) unpack2(accp[j][x], rlo[x], rhi[x]);
        #pragma unroll
        for (int half = 0; half < 2; half++) {
            const float* r = half ? rhi : rlo;
            int gr = bm + trow + 2 * j + half;
            if (gr < M) {
                #pragma unroll
                for (int x = 0; x < 8; x += 4) {
                    float4 v;
                    v.x = r[x + 0] + bias[bn + tcol + x + 0];
                    v.y = r[x + 1] + bias[bn + tcol + x + 1];
                    v.z = r[x + 2] + bias[bn + tcol + x + 2];
                    v.w = r[x + 3] + bias[bn + tcol + x + 3];
                    if (ACT) {
                        v.x = leaky_f(v.x); v.y = leaky_f(v.y);
                        v.z = leaky_f(v.z); v.w = leaky_f(v.w);
                    }
                    *(float4*)(C + (size_t)gr * N + bn + tcol + x) = v;
                }
            }
        }
    }
}

// ---------------- edge scoring: logits + segment max ----------------
// warp per edge: lh = leaky(nodeL[src]+relL+qtabL); rp = leaky(nodeR[dst]+relR+qtabR)
// rh = rp @ Wc + bc;  logit = dot(lh, rh);  atomicMax over src.
__global__ void __launch_bounds__(256) edgeA_kernel(
    const int* __restrict__ src_idx, const int* __restrict__ dst_idx,
    const int* __restrict__ eg_idx, const float* __restrict__ Wc,
    const float* __restrict__ bc, int E) {
    __shared__ float Wcs[64][64];
    __shared__ float bcs[64];
    __shared__ float rbuf[8][64];
    const int tid = threadIdx.x;
    for (int i = tid; i < 4096; i += 256) Wcs[i >> 6][i & 63] = Wc[i];
    if (tid < 64) bcs[tid] = bc[tid];
    __syncthreads();
    const int warp = tid >> 5, lane = tid & 31;
    for (int e = blockIdx.x * 8 + warp; e < E; e += gridDim.x * 8) {
        int src = src_idx[e], dst = dst_idx[e], eg = eg_idx[e];
        const float* nl = g_nodeLR + (size_t)src * 128;
        const float* nr = g_nodeLR + (size_t)dst * 128;
        const float* rl = g_relLR + (size_t)e * 128;
        const float* qt = g_qtab + eg * 128;
        float lh0 = leaky_f(nl[lane]      + rl[lane]      + qt[lane]);
        float lh1 = leaky_f(nl[lane + 32] + rl[lane + 32] + qt[lane + 32]);
        float r0  = leaky_f(nr[lane + 64] + rl[lane + 64] + qt[lane + 64]);
        float r1  = leaky_f(nr[lane + 96] + rl[lane + 96] + qt[lane + 96]);
        rbuf[warp][lane] = r0;
        rbuf[warp][lane + 32] = r1;
        __syncwarp();
        float rh0 = bcs[lane], rh1 = bcs[lane + 32];
        #pragma unroll 16
        for (int k = 0; k < 64; k++) {
            float rv = rbuf[warp][k];
            rh0 += rv * Wcs[k][lane];
            rh1 += rv * Wcs[k][lane + 32];
        }
        float p = lh0 * rh0 + lh1 * rh1;
        #pragma unroll
        for (int off = 16; off; off >>= 1) p += __shfl_xor_sync(0xffffffffu, p, off);
        if (lane == 0) {
            g_logits[e] = p;
            atomicMax(&g_segmax[src], fkey(p));
        }
        __syncwarp();
    }
}

// ---------------- softmax + fused propagation/aggregation ----------------
__global__ void edgeB_kernel(const int* __restrict__ src_idx, int E) {
    int e = blockIdx.x * blockDim.x + threadIdx.x;
    if (e >= E) return;
    int s = src_idx[e];
    float mx = funkey(g_segmax[s]);
    float ex = expf(g_logits[e] - mx);
    g_ex[e] = ex;
    atomicAdd(&g_denom[s], ex);
}

// fused: out[entity[dst]] += trans * score[src]  (segment_sum∘segment_sum == direct scatter)
__global__ void edgeC_kernel(const int* __restrict__ src_idx, const int* __restrict__ dst_idx,
                             const int* __restrict__ entity_idx,
                             const float* __restrict__ node_score,
                             float* __restrict__ out, int E) {
    int e = blockIdx.x * blockDim.x + threadIdx.x;
    if (e >= E) return;
    int s = src_idx[e];
    float trans = g_ex[e] / g_denom[s];
    atomicAdd(&out[entity_idx[dst_idx[e]]], trans * node_score[s]);
}

// ---------------- launch ----------------
extern "C" void kernel_launch(void* const* d_in, const int* in_sizes, int n_in,
                              void* d_out, int out_size) {
    const float* mem        = (const float*)d_in[0];
    const float* node_score = (const float*)d_in[1];
    const float* rel        = (const float*)d_in[2];
    const float* qse        = (const float*)d_in[3];
    const float* qre        = (const float*)d_in[4];
    const int*   eg         = (const int*)d_in[5];
    const int*   srcI       = (const int*)d_in[6];
    const int*   dstI       = (const int*)d_in[7];
    const int*   ent        = (const int*)d_in[8];
    const float* W_proj     = (const float*)d_in[9];
    const float* b_proj     = (const float*)d_in[10];
    const float* W_static   = (const float*)d_in[11];
    const float* b_static   = (const float*)d_in[12];
    const float* W_bs       = (const float*)d_in[13];
    const float* b_bs       = (const float*)d_in[14];
    const float* Wl         = (const float*)d_in[15];
    const float* bl         = (const float*)d_in[16];
    const float* Wr         = (const float*)d_in[17];
    const float* br         = (const float*)d_in[18];
    const float* Wc         = (const float*)d_in[19];
    const float* bc         = (const float*)d_in[20];
    float* out = (float*)d_out;

    const int Nn = in_sizes[1];  // 200000 nodes
    const int E  = in_sizes[5];  // 300000 edges

    float *p_emb2, *p_C, *p_cb, *p_nodeLR, *p_D, *p_db, *p_relLR;
    cudaGetSymbolAddress((void**)&p_emb2,   g_emb2);
    cudaGetSymbolAddress((void**)&p_C,      g_Cmat);
    cudaGetSymbolAddress((void**)&p_cb,     g_cb);
    cudaGetSymbolAddress((void**)&p_nodeLR, g_nodeLR);
    cudaGetSymbolAddress((void**)&p_D,      g_Dmat);
    cudaGetSymbolAddress((void**)&p_db,     g_db);
    cudaGetSymbolAddress((void**)&p_relLR,  g_relLR);

    int initN = Nn > out_size ? Nn : out_size;
    init_kernel<<<(initN + 255) / 256, 256>>>(out, Nn, out_size);
    prep1_kernel<<<(78080 + 255) / 256, 256>>>(W_proj, b_proj, W_static, b_static, Wl, Wr, qse, qre);
    prep2_kernel<<<64, 256>>>(Wl, bl, Wr, br);

    dim3 g1(2, (Nn + 127) / 128);
    gemm_kernel<1><<<g1, 256>>>(mem, W_bs, b_bs, p_emb2, Nn, 256, 256);
    dim3 g2(1, (Nn + 127) / 128);
    gemm_kernel<0><<<g2, 256>>>(p_emb2, p_C, p_cb, p_nodeLR, Nn, 128, 256);
    dim3 g3(1, (E + 127) / 128);
    gemm_kernel<0><<<g3, 256>>>(rel, p_D, p_db, p_relLR, E, 128, 256);

    // bounded grid + grid-stride: stage Wc once per resident block
    int edgeA_blocks = 2368;
    int need = (E + 7) / 8;
    if (need < edgeA_blocks) edgeA_blocks = need;
    edgeA_kernel<<<edgeA_blocks, 256>>>(srcI, dstI, eg, Wc, bc, E);
    edgeB_kernel<<<(E + 255) / 256, 256>>>(srcI, E);
    edgeC_kernel<<<(E + 255) / 256, 256>>>(srcI, dstI, ent, node_score, out, E);
}

// round 12
// speedup vs baseline: 1.1449x; 1.1449x over previous
#include <cuda_runtime.h>

// ---------------- static device scratch (no allocations allowed) ----------------
#define NN_MAX 200000
#define NE_MAX 300000

__device__ __align__(16) float g_emb2[(size_t)NN_MAX * 256];    // leaky(mem@W_bs+b)
__device__ __align__(16) float g_nodeLR[(size_t)NN_MAX * 128];  // [nodeL | nodeR]
__device__ __align__(16) float g_relLR[(size_t)NE_MAX * 128];   // [relL | relR]
__device__ __align__(16) float g_Cmat[256 * 128];               // W_proj@[Wl_a | Wr_a]
__device__ __align__(16) float g_Dmat[256 * 128];               // W_proj@[Wl_b | Wr_b]
__device__ __align__(16) float g_cb[128];
__device__ __align__(16) float g_db[128];
__device__ __align__(16) float g_qs[128 * 32];
__device__ __align__(16) float g_qr[128 * 64];
__device__ __align__(16) float g_qtab[128 * 128];               // per-query [L|R] additive table
__device__ float g_logits[NE_MAX];
__device__ float g_ex[NE_MAX];
__device__ unsigned g_segmax[NN_MAX];
__device__ float g_denom[NN_MAX];

__device__ __forceinline__ float leaky_f(float x) { return x > 0.f ? x : 0.01f * x; }

// order-preserving float->uint key for atomicMax
__device__ __forceinline__ unsigned fkey(float f) {
    int i = __float_as_int(f);
    return (i >= 0) ? ((unsigned)i | 0x80000000u) : ~(unsigned)i;
}
__device__ __forceinline__ float funkey(unsigned u) {
    int i = (u & 0x80000000u) ? (int)(u & 0x7FFFFFFFu) : ~(int)u;
    return __int_as_float(i);
}

// ---- packed fp32x2 helpers (Blackwell FFMA2 path) ----
__device__ __forceinline__ unsigned long long pack_dup(float v) {
    unsigned long long r;
    asm("mov.b64 %0, {%1, %1};" : "=l"(r) : "f"(v));
    return r;
}
__device__ __forceinline__ void ffma2(unsigned long long& d, unsigned long long a,
                                      unsigned long long b) {
    asm("fma.rn.f32x2 %0, %1, %2, %0;" : "+l"(d) : "l"(a), "l"(b));
}
__device__ __forceinline__ void unpack2(unsigned long long v, float& lo, float& hi) {
    asm("mov.b64 {%0, %1}, %2;" : "=f"(lo), "=f"(hi) : "l"(v));
}

// aligned 32-byte operand bundle: float4x2 view for LDS.128, u64 view for FFMA2
union __align__(16) Vec8 {
    float4 v4[2];
    float f[8];
    unsigned long long u2[4];
};

// ---------------- init ----------------
__global__ void init_kernel(float* __restrict__ out, int Nn, int Osz) {
    int i = blockIdx.x * blockDim.x + threadIdx.x;
    if (i < Nn) { g_denom[i] = 0.f; g_segmax[i] = 0u; }
    if (i < Osz) out[i] = 0.f;
}

// ---------------- prep: fold small matrices ----------------
__global__ void prep1_kernel(const float* __restrict__ W_proj, const float* __restrict__ b_proj,
                             const float* __restrict__ W_static, const float* __restrict__ b_static,
                             const float* __restrict__ Wl, const float* __restrict__ Wr,
                             const float* __restrict__ qse, const float* __restrict__ qre) {
    int idx = blockIdx.x * blockDim.x + threadIdx.x;
    if (idx < 32768) {
        int k = idx >> 7, j = idx & 127;
        const float* W = (j < 64) ? Wl : Wr; int jj = j & 63;
        float s = 0.f;
        #pragma unroll 8
        for (int m = 0; m < 64; m++) s += W_proj[k * 64 + m] * W[m * 64 + jj];
        g_Cmat[k * 128 + j] = s;
    } else if (idx < 65536) {
        int t = idx - 32768; int k = t >> 7, j = t & 127;
        const float* W = (j < 64) ? Wl : Wr; int jj = j & 63;
        float s = 0.f;
        #pragma unroll 8
        for (int m = 0; m < 64; m++) s += W_proj[k * 64 + m] * W[(64 + m) * 64 + jj];
        g_Dmat[k * 128 + j] = s;
    } else if (idx < 65664) {
        int j = idx - 65536; const float* W = (j < 64) ? Wl : Wr; int jj = j & 63;
        float s = 0.f;
        for (int m = 0; m < 64; m++) s += b_proj[m] * W[m * 64 + jj];
        g_cb[j] = s;
    } else if (idx < 65792) {
        int j = idx - 65664; const float* W = (j < 64) ? Wl : Wr; int jj = j & 63;
        float s = 0.f;
        for (int m = 0; m < 64; m++) s += b_proj[m] * W[(64 + m) * 64 + jj];
        g_db[j] = s;
    } else if (idx < 69888) {
        int t2 = idx - 65792; int q = t2 >> 5, t = t2 & 31;
        float s = b_static[t];
        for (int k = 0; k < 128; k++) s += qse[q * 128 + k] * W_static[k * 32 + t];
        g_qs[q * 32 + t] = s;
    } else if (idx < 78080) {
        int t2 = idx - 69888; int q = t2 >> 6, m = t2 & 63;
        float s = b_proj[m];
        for (int k = 0; k < 256; k++) s += qre[q * 256 + k] * W_proj[k * 64 + m];
        g_qr[q * 64 + m] = s;
    }
}

__global__ void prep2_kernel(const float* __restrict__ Wl, const float* __restrict__ bl,
                             const float* __restrict__ Wr, const float* __restrict__ br) {
    int idx = blockIdx.x * blockDim.x + threadIdx.x;
    if (idx >= 16384) return;
    int q = idx >> 7, j = idx & 127;
    const float *W, *b; int jj;
    if (j < 64) { W = Wl; b = bl; jj = j; } else { W = Wr; b = br; jj = j - 64; }
    float s = b[jj];
    for (int t = 0; t < 32; t++) s += g_qs[q * 32 + t] * W[(128 + t) * 64 + jj];
    for (int m = 0; m < 64; m++) s += g_qr[q * 64 + m] * W[(160 + m) * 64 + jj];
    g_qtab[q * 128 + j] = s;
}

// ---------------- tiled fp32 GEMM: FFMA2, conflict-free B fragments ------------
// C = act(A[MxK] @ B[KxN] + bias[N]); BM=BN=128, BK=16, 256 thr, 8x8 reg tile.
// Thread's 8 columns are split stride-4: {4g..4g+3} U {4g+64..4g+67} so each
// quarter-warp's Bs LDS.128 addresses hit all 32 banks exactly once (the old
// contiguous tcol*8 mapping had a 2-way conflict on every bv load -> L1 88%).
template <int ACT>
__global__ void __launch_bounds__(256, 2) gemm_kernel(
    const float* __restrict__ A, const float* __restrict__ B,
    const float* __restrict__ bias, float* __restrict__ C,
    int M, int N, int K) {
    __shared__ float As[2][16][132];  // transposed tile, padded
    __shared__ float Bs[2][16][128];
    const int tid = threadIdx.x;
    const int bm = blockIdx.y << 7;
    const int bn = blockIdx.x << 7;
    const int trow = (tid >> 4) << 3;
    const int tcol0 = (tid & 15) << 2;   // stride-4 column base; 2nd group at +64

    // per-thread load coordinates (2 float4 each for A and B)
    const int ar0 = tid >> 2,          ac0 = (tid & 3) << 2;   // A part 0
    const int ar1 = (tid + 256) >> 2,  ac1 = ac0;               // A part 1
    const int br0 = tid >> 5,          bc0 = (tid & 31) << 2;   // B part 0
    const int br1 = (tid + 256) >> 5,  bc1 = bc0;               // B part 1

    // packed accumulators: accp[j][x] holds rows (trow+2j, trow+2j+1);
    // col(x) = tcol0+x for x<4, tcol0+64+(x-4) for x>=4
    unsigned long long accp[4][8];
    #pragma unroll
    for (int j = 0; j < 4; j++)
        #pragma unroll
        for (int x = 0; x < 8; x++) accp[j][x] = 0ull;

    // prologue: fetch tile 0, commit to buffer 0
    float4 a0 = make_float4(0.f,0.f,0.f,0.f), a1 = a0, b0, b1;
    if (bm + ar0 < M) a0 = *(const float4*)(A + (size_t)(bm + ar0) * K + ac0);
    if (bm + ar1 < M) a1 = *(const float4*)(A + (size_t)(bm + ar1) * K + ac1);
    b0 = *(const float4*)(B + (size_t)br0 * N + bn + bc0);
    b1 = *(const float4*)(B + (size_t)br1 * N + bn + bc1);
    As[0][ac0 + 0][ar0] = a0.x; As[0][ac0 + 1][ar0] = a0.y;
    As[0][ac0 + 2][ar0] = a0.z; As[0][ac0 + 3][ar0] = a0.w;
    As[0][ac1 + 0][ar1] = a1.x; As[0][ac1 + 1][ar1] = a1.y;
    As[0][ac1 + 2][ar1] = a1.z; As[0][ac1 + 3][ar1] = a1.w;
    *(float4*)&Bs[0][br0][bc0] = b0;
    *(float4*)&Bs[0][br1][bc1] = b1;
    __syncthreads();

    int s = 0;
    for (int k0 = 0; k0 < K; k0 += 16) {
        const int kn = k0 + 16;
        // prefetch next tile into registers (overlaps the FMA loop)
        if (kn < K) {
            a0 = make_float4(0.f,0.f,0.f,0.f); a1 = a0;
            if (bm + ar0 < M) a0 = *(const float4*)(A + (size_t)(bm + ar0) * K + kn + ac0);
            if (bm + ar1 < M) a1 = *(const float4*)(A + (size_t)(bm + ar1) * K + kn + ac1);
            b0 = *(const float4*)(B + (size_t)(kn + br0) * N + bn + bc0);
            b1 = *(const float4*)(B + (size_t)(kn + br1) * N + bn + bc1);
        }

        #pragma unroll
        for (int k = 0; k < 16; k++) {
            Vec8 av, bv;   // aligned unions: LDS.128 in, row-pair u64 out
            av.v4[0] = *(const float4*)&As[s][k][trow];
            av.v4[1] = *(const float4*)&As[s][k][trow + 4];
            bv.v4[0] = *(const float4*)&Bs[s][k][tcol0];        // banks 4g: conflict-free
            bv.v4[1] = *(const float4*)&Bs[s][k][tcol0 + 64];   // banks 4g: conflict-free
            unsigned long long bd[8];
            #pragma unroll
            for (int x = 0; x < 8; x++) bd[x] = pack_dup(bv.f[x]);
            #pragma unroll
            for (int j = 0; j < 4; j++)
                #pragma unroll
                for (int x = 0; x < 8; x++) ffma2(accp[j][x], av.u2[j], bd[x]);
        }

        // commit prefetched tile to the other buffer
        if (kn < K) {
            const int t = s ^ 1;
            As[t][ac0 + 0][ar0] = a0.x; As[t][ac0 + 1][ar0] = a0.y;
            As[t][ac0 + 2][ar0] = a0.z; As[t][ac0 + 3][ar0] = a0.w;
            As[t][ac1 + 0][ar1] = a1.x; As[t][ac1 + 1][ar1] = a1.y;
            As[t][ac1 + 2][ar1] = a1.z; As[t][ac1 + 3][ar1] = a1.w;
            *(float4*)&Bs[t][br0][bc0] = b0;
            *(float4*)&Bs[t][br1][bc1] = b1;
            __syncthreads();
            s = t;
        }
    }

    #pragma unroll
    for (int j = 0; j < 4; j++) {
        float rlo[8], rhi[8];
        #pragma unroll
        for (int x = 0; x < 8; x++) unpack2(accp[j][x], rlo[x], rhi[x]);
        #pragma unroll
        for (int half = 0; half < 2; half++) {
            const float* r = half ? rhi : rlo;
            int gr = bm + trow + 2 * j + half;
            if (gr < M) {
                #pragma unroll
                for (int grp = 0; grp < 2; grp++) {
                    const int cbase = bn + tcol0 + grp * 64;
                    const int xb = grp * 4;
                    float4 v;
                    v.x = r[xb + 0] + bias[cbase + 0];
                    v.y = r[xb + 1] + bias[cbase + 1];
                    v.z = r[xb + 2] + bias[cbase + 2];
                    v.w = r[xb + 3] + bias[cbase + 3];
                    if (ACT) {
                        v.x = leaky_f(v.x); v.y = leaky_f(v.y);
                        v.z = leaky_f(v.z); v.w = leaky_f(v.w);
                    }
                    *(float4*)(C + (size_t)gr * N + cbase) = v;
                }
            }
        }
    }
}

// ---------------- edge scoring: logits + segment max ----------------
__global__ void __launch_bounds__(256) edgeA_kernel(
    const int* __restrict__ src_idx, const int* __restrict__ dst_idx,
    const int* __restrict__ eg_idx, const float* __restrict__ Wc,
    const float* __restrict__ bc, int E) {
    __shared__ float Wcs[64][64];
    __shared__ float bcs[64];
    __shared__ float rbuf[8][64];
    const int tid = threadIdx.x;
    for (int i = tid; i < 4096; i += 256) Wcs[i >> 6][i & 63] = Wc[i];
    if (tid < 64) bcs[tid] = bc[tid];
    __syncthreads();
    const int warp = tid >> 5, lane = tid & 31;
    for (int e = blockIdx.x * 8 + warp; e < E; e += gridDim.x * 8) {
        int src = src_idx[e], dst = dst_idx[e], eg = eg_idx[e];
        const float* nl = g_nodeLR + (size_t)src * 128;
        const float* nr = g_nodeLR + (size_t)dst * 128;
        const float* rl = g_relLR + (size_t)e * 128;
        const float* qt = g_qtab + eg * 128;
        float lh0 = leaky_f(nl[lane]      + rl[lane]      + qt[lane]);
        float lh1 = leaky_f(nl[lane + 32] + rl[lane + 32] + qt[lane + 32]);
        float r0  = leaky_f(nr[lane + 64] + rl[lane + 64] + qt[lane + 64]);
        float r1  = leaky_f(nr[lane + 96] + rl[lane + 96] + qt[lane + 96]);
        rbuf[warp][lane] = r0;
        rbuf[warp][lane + 32] = r1;
        __syncwarp();
        float rh0 = bcs[lane], rh1 = bcs[lane + 32];
        #pragma unroll 16
        for (int k = 0; k < 64; k++) {
            float rv = rbuf[warp][k];
            rh0 += rv * Wcs[k][lane];
            rh1 += rv * Wcs[k][lane + 32];
        }
        float p = lh0 * rh0 + lh1 * rh1;
        #pragma unroll
        for (int off = 16; off; off >>= 1) p += __shfl_xor_sync(0xffffffffu, p, off);
        if (lane == 0) {
            g_logits[e] = p;
            atomicMax(&g_segmax[src], fkey(p));
        }
        __syncwarp();
    }
}

// ---------------- softmax + fused propagation/aggregation ----------------
__global__ void edgeB_kernel(const int* __restrict__ src_idx, int E) {
    int e = blockIdx.x * blockDim.x + threadIdx.x;
    if (e >= E) return;
    int s = src_idx[e];
    float mx = funkey(g_segmax[s]);
    float ex = expf(g_logits[e] - mx);
    g_ex[e] = ex;
    atomicAdd(&g_denom[s], ex);
}

// fused: out[entity[dst]] += trans * score[src]  (segment_sum∘segment_sum == direct scatter)
__global__ void edgeC_kernel(const int* __restrict__ src_idx, const int* __restrict__ dst_idx,
                             const int* __restrict__ entity_idx,
                             const float* __restrict__ node_score,
                             float* __restrict__ out, int E) {
    int e = blockIdx.x * blockDim.x + threadIdx.x;
    if (e >= E) return;
    int s = src_idx[e];
    float trans = g_ex[e] / g_denom[s];
    atomicAdd(&out[entity_idx[dst_idx[e]]], trans * node_score[s]);
}

// ---------------- launch ----------------
extern "C" void kernel_launch(void* const* d_in, const int* in_sizes, int n_in,
                              void* d_out, int out_size) {
    const float* mem        = (const float*)d_in[0];
    const float* node_score = (const float*)d_in[1];
    const float* rel        = (const float*)d_in[2];
    const float* qse        = (const float*)d_in[3];
    const float* qre        = (const float*)d_in[4];
    const int*   eg         = (const int*)d_in[5];
    const int*   srcI       = (const int*)d_in[6];
    const int*   dstI       = (const int*)d_in[7];
    const int*   ent        = (const int*)d_in[8];
    const float* W_proj     = (const float*)d_in[9];
    const float* b_proj     = (const float*)d_in[10];
    const float* W_static   = (const float*)d_in[11];
    const float* b_static   = (const float*)d_in[12];
    const float* W_bs       = (const float*)d_in[13];
    const float* b_bs       = (const float*)d_in[14];
    const float* Wl         = (const float*)d_in[15];
    const float* bl         = (const float*)d_in[16];
    const float* Wr         = (const float*)d_in[17];
    const float* br         = (const float*)d_in[18];
    const float* Wc         = (const float*)d_in[19];
    const float* bc         = (const float*)d_in[20];
    float* out = (float*)d_out;

    const int Nn = in_sizes[1];  // 200000 nodes
    const int E  = in_sizes[5];  // 300000 edges

    float *p_emb2, *p_C, *p_cb, *p_nodeLR, *p_D, *p_db, *p_relLR;
    cudaGetSymbolAddress((void**)&p_emb2,   g_emb2);
    cudaGetSymbolAddress((void**)&p_C,      g_Cmat);
    cudaGetSymbolAddress((void**)&p_cb,     g_cb);
    cudaGetSymbolAddress((void**)&p_nodeLR, g_nodeLR);
    cudaGetSymbolAddress((void**)&p_D,      g_Dmat);
    cudaGetSymbolAddress((void**)&p_db,     g_db);
    cudaGetSymbolAddress((void**)&p_relLR,  g_relLR);

    int initN = Nn > out_size ? Nn : out_size;
    init_kernel<<<(initN + 255) / 256, 256>>>(out, Nn, out_size);
    prep1_kernel<<<(78080 + 255) / 256, 256>>>(W_proj, b_proj, W_static, b_static, Wl, Wr, qse, qre);
    prep2_kernel<<<64, 256>>>(Wl, bl, Wr, br);

    dim3 g1(2, (Nn + 127) / 128);
    gemm_kernel<1><<<g1, 256>>>(mem, W_bs, b_bs, p_emb2, Nn, 256, 256);
    dim3 g2(1, (Nn + 127) / 128);
    gemm_kernel<0><<<g2, 256>>>(p_emb2, p_C, p_cb, p_nodeLR, Nn, 128, 256);
    dim3 g3(1, (E + 127) / 128);
    gemm_kernel<0><<<g3, 256>>>(rel, p_D, p_db, p_relLR, E, 128, 256);

    // bounded grid + grid-stride: stage Wc once per resident block
    int edgeA_blocks = 2368;
    int need = (E + 7) / 8;
    if (need < edgeA_blocks) edgeA_blocks = need;
    edgeA_kernel<<<edgeA_blocks, 256>>>(srcI, dstI, eg, Wc, bc, E);
    edgeB_kernel<<<(E + 255) / 256, 256>>>(srcI, E);
    edgeC_kernel<<<(E + 255) / 256, 256>>>(srcI, dstI, ent, node_score, out, E);
}